// round 6
// baseline (speedup 1.0000x reference)
#include <cuda_runtime.h>
#include <math.h>

// ChfLoss: B=8, H=W=64, P=60. loss = (0.1/B) * sum_b ||CHF(dnn_b - gt_b)||_2
// Separable trig: angle[p,q,(i,j)] = r_q*x_i + r_p*y_j, x_axis == y_axis.
// ONE kernel, NO device-wide trig barrier: each block computes the full
// 3840-entry trig table into its own shared memory (~500 cycles via MUFU),
// overlapped with the global loads of D.

#define NB      8
#define HWD     64
#define PP      60
#define PTILES  15                  // 60 / 4 p-rows per block
#define NBLK    (NB * PTILES)       // 120

// __device__ globals = sanctioned scratch (no allocation allowed)
__device__ float    g_part[NBLK];         // per-block partial sum of squares
__device__ unsigned g_count = 0;          // epilogue counter (self-resetting)

// Shared: D 4096 + CS 7680 + A 512 = 12288 floats = 48KB dynamic exactly.
// NO static __shared__ anywhere (would exceed the 48KB default limit).
__global__ __launch_bounds__(256) void chf_fused_kernel(const float* __restrict__ dnn,
                                                        const float* __restrict__ gt,
                                                        float* __restrict__ out) {
    extern __shared__ float sm[];
    float*  sD  = sm;                               // [j*64 + i]
    float2* sCS = (float2*)(sm + 4096);             // [i*60 + q] (also [j*60 + p])
    float2* sA  = (float2*)(sm + 4096 + 7680);      // [i*4 + pl]

    const int blk = blockIdx.x;
    const int b   = blk / PTILES;
    const int pt  = blk - b * PTILES;
    const int p0  = pt * 4;
    const int t   = threadIdx.x;

    // ---- issue global loads FIRST (latency hidden by trig compute below) ----
    const float4* d4 = (const float4*)(dnn + b * 4096);
    const float4* g4 = (const float4*)(gt  + b * 4096);
    float4 va[4], vg[4];
    #pragma unroll
    for (int k = 0; k < 4; k++) {
        va[k] = d4[t + k * 256];
        vg[k] = g4[t + k * 256];
    }

    // ---- full trig table, block-private, 15 entries/thread ----
    // Reference: angle = fl(r_q * x_i) in fp32, then cos/sin. Exact fp32
    // Cody-Waite: k = rint(a/2pi) (k<=243, exact); fma(-k, 6.28125f, a) is
    // EXACT (both multiples of 2^-13, |diff|<=3.6); second fma adds ~3e-7 rad
    // error. __sincosf on |ar|<=pi: ~5e-7 abs. Loss rel_err ~1e-6 << 1e-3.
    {
        const float inv2pi = 0.15915494309189535f;
        const float C1 = 6.28125f;                   // 201/32, exact
        const float C2 = 1.9353071795864769e-3f;     // 2*pi - C1
        #pragma unroll
        for (int k = 0; k < 15; k++) {
            int e = t + k * 256;                     // 0..3839 = i*60 + q
            int i = e / 60;
            int q = e - i * 60;
            float r  = (float)(q - 30) * 0.1f;       // fp32 grid, matches ref
            float x  = (float)(4 + 8 * i);           // linspace(4,508,64), exact
            float a  = r * x;                        // ref's fp32 angle
            float kk = rintf(a * inv2pi);
            float ar = fmaf(-kk, C1, a);             // exact
            ar       = fmaf(-kk, C2, ar);            // |ar| <= pi (+eps)
            float s, c;
            __sincosf(ar, &s, &c);
            sCS[e] = make_float2(c, s);              // consecutive -> conflict-free
        }
    }

    // ---- D = dnn - gt into shared ----
    {
        float4* sD4 = (float4*)sD;
        #pragma unroll
        for (int k = 0; k < 4; k++) {
            sD4[t + k * 256] = make_float4(va[k].x - vg[k].x, va[k].y - vg[k].y,
                                           va[k].z - vg[k].z, va[k].w - vg[k].w);
        }
    }
    __syncthreads();

    // ---- stage 1: thread t -> (pl = t>>6, i = t&63), p = p0+pl ----
    {
        const int pl = t >> 6;
        const int i  = t & 63;
        const int p  = p0 + pl;
        float ac = 0.f, as = 0.f;
        #pragma unroll 16
        for (int j = 0; j < 64; j++) {
            float  d  = sD[j * 64 + i];      // conflict-free (i = lane)
            float2 cs = sCS[j * PP + p];     // 64-bit broadcast (p uniform per warp)
            ac = fmaf(cs.x, d, ac);
            as = fmaf(cs.y, d, as);
        }
        sA[i * 4 + pl] = make_float2(ac, as);
    }
    __syncthreads();

    // ---- stage 2: threads 0..239 -> (pl = t/60, q = t%60) ----
    // Split accumulator chains: dependent depth 64 instead of 128.
    float re1 = 0.f, re2 = 0.f, im1 = 0.f, im2 = 0.f;
    if (t < 240) {
        const int pl = t / 60;
        const int q  = t - pl * 60;
        #pragma unroll 16
        for (int i = 0; i < 64; i++) {
            float2 a  = sA[i * 4 + pl];      // 64-bit broadcast
            float2 cs = sCS[i * PP + q];     // consecutive q -> conflict-free
            re1 = fmaf(a.x, cs.x, re1);
            re2 = fmaf(a.y, cs.y, re2);
            im1 = fmaf(a.y, cs.x, im1);
            im2 = fmaf(a.x, cs.y, im2);
        }
    }
    float re = re1 - re2;
    float im = im1 + im2;
    float v  = fmaf(re, re, im * im);

    // ---- block reduce sum of squares ----
    #pragma unroll
    for (int off = 16; off > 0; off >>= 1)
        v += __shfl_down_sync(0xFFFFFFFFu, v, off);

    __syncthreads();                       // stage-2 smem reads done; reuse sD
    if ((t & 31) == 0) sD[t >> 5] = v;     // 8 warp partials
    __syncthreads();
    if (t == 0) {
        float s = 0.f;
        #pragma unroll
        for (int w = 0; w < 8; w++) s += sD[w];
        g_part[blk] = s;
        __threadfence();                   // release g_part before counter bump
        unsigned c = atomicAdd(&g_count, 1u);
        bool last = (c == NBLK - 1);
        if (last) g_count = 0;             // reset for next graph replay
        sD[8] = last ? 1.f : 0.f;          // flag via dynamic smem (no static shared)
    }
    __syncthreads();

    // ---- last block: deterministic finalize ----
    if (sD[8] != 0.f) {
        __threadfence();                   // acquire: all g_part visible
        float w = 0.f;
        if (t < NB) {
            float s = 0.f;
            #pragma unroll
            for (int k = 0; k < PTILES; k++)
                s += g_part[t * PTILES + k];   // fixed order -> deterministic
            w = sqrtf(s);
        }
        if (t < 32) {
            #pragma unroll
            for (int off = 16; off > 0; off >>= 1)
                w += __shfl_down_sync(0xFFFFFFFFu, w, off);
            if (t == 0) out[0] = w * 0.1f / 8.0f;
        }
    }
}

// ---------------------------------------------------------------------------
extern "C" void kernel_launch(void* const* d_in, const int* in_sizes, int n_in,
                              void* d_out, int out_size) {
    (void)in_sizes; (void)n_in; (void)out_size;
    const float* dnn = (const float*)d_in[0];
    const float* gt  = (const float*)d_in[1];
    float* out = (float*)d_out;

    chf_fused_kernel<<<NBLK, 256, 12288 * sizeof(float)>>>(dnn, gt, out);
}

// round 7
// speedup vs baseline: 1.3872x; 1.3872x over previous
#include <cuda_runtime.h>
#include <math.h>

// ChfLoss: B=8, H=W=64, P=60. loss = (0.1/B) * sum_b ||CHF(dnn_b - gt_b)||_2
// Separable trig: angle[p,q,(i,j)] = r_q*x_i + r_p*y_j, x_axis == y_axis.
// ONE kernel, no device-wide barrier: each block computes the full 3840-entry
// trig table into its own shared memory (MUFU, ~500 cyc, overlapped with the
// global loads of D). 512 threads: adjacent lane pairs split the inner loops
// (chain depth 64 -> 32) and combine with one shfl_xor (commutative -> exact).

#define NB      8
#define HWD     64
#define PP      60
#define PTILES  15                  // 60 / 4 p-rows per block
#define NBLK    (NB * PTILES)       // 120
#define NT      512

// __device__ globals = sanctioned scratch (no allocation allowed)
__device__ float    g_part[NBLK];         // per-block partial sum of squares
__device__ unsigned g_count = 0;          // epilogue counter (self-resetting)

// Shared: D 4096 + CS 7680 + A 512 = 12288 floats = 48KB dynamic exactly.
// NO static __shared__ anywhere (would exceed the 48KB default limit).
__global__ __launch_bounds__(NT) void chf_fused_kernel(const float* __restrict__ dnn,
                                                       const float* __restrict__ gt,
                                                       float* __restrict__ out) {
    extern __shared__ float sm[];
    float*  sD  = sm;                               // [j*64 + i]
    float2* sCS = (float2*)(sm + 4096);             // [i*60 + q] (also [j*60 + p])
    float2* sA  = (float2*)(sm + 4096 + 7680);      // [i*4 + pl]

    const int blk = blockIdx.x;
    const int b   = blk / PTILES;
    const int pt  = blk - b * PTILES;
    const int p0  = pt * 4;
    const int t   = threadIdx.x;
    const int tt   = t >> 1;                        // pair index
    const int half = t & 1;                         // which half of inner loop

    // ---- issue global loads FIRST (latency hidden by trig compute below) ----
    const float4* d4 = (const float4*)(dnn + b * 4096);
    const float4* g4 = (const float4*)(gt  + b * 4096);
    float4 va[2], vg[2];
    #pragma unroll
    for (int k = 0; k < 2; k++) {
        va[k] = d4[t + k * NT];
        vg[k] = g4[t + k * NT];
    }

    // ---- full trig table, block-private ----
    // Reference: angle = fl(r_q * x_i) in fp32, then cos/sin. Exact fp32
    // Cody-Waite: k = rint(a/2pi) (|k|<=243, exact); fma(-k, 6.28125f, a) is
    // EXACT (both multiples of 2^-13, |diff|<=3.6); second fma adds ~3e-7 rad.
    // __sincosf on |ar|<=pi: ~5e-7 abs. Loss rel_err ~1e-6 << 1e-3.
    {
        const float inv2pi = 0.15915494309189535f;
        const float C1 = 6.28125f;                   // 201/32, exact
        const float C2 = 1.9353071795864769e-3f;     // 2*pi - C1
        #pragma unroll
        for (int k = 0; k < 8; k++) {
            int e = t + k * NT;                      // 0..4095; table is 3840
            if (e < HWD * PP) {
                int i = e / 60;
                int q = e - i * 60;
                float r  = (float)(q - 30) * 0.1f;   // fp32 grid, matches ref
                float x  = (float)(4 + 8 * i);       // linspace(4,508,64), exact
                float a  = r * x;                    // ref's fp32 angle
                float kk = rintf(a * inv2pi);
                float ar = fmaf(-kk, C1, a);         // exact
                ar       = fmaf(-kk, C2, ar);        // |ar| <= pi (+eps)
                float s, c;
                __sincosf(ar, &s, &c);
                sCS[e] = make_float2(c, s);          // consecutive -> conflict-free
            }
        }
    }

    // ---- D = dnn - gt into shared ----
    {
        float4* sD4 = (float4*)sD;
        #pragma unroll
        for (int k = 0; k < 2; k++) {
            sD4[t + k * NT] = make_float4(va[k].x - vg[k].x, va[k].y - vg[k].y,
                                          va[k].z - vg[k].z, va[k].w - vg[k].w);
        }
    }
    __syncthreads();

    // ---- stage 1: pair tt -> (pl = tt>>6, i = tt&63); halves split j ----
    {
        const int pl = tt >> 6;                      // uniform per warp
        const int i  = tt & 63;
        const int p  = p0 + pl;
        const int j0 = half * 32;
        float ac = 0.f, as = 0.f;
        #pragma unroll 16
        for (int jj = 0; jj < 32; jj++) {
            int j = j0 + jj;
            float  d  = sD[j * 64 + i];      // paired broadcast, conflict-free
            float2 cs = sCS[j * PP + p];     // 2 addrs/warp, broadcast
            ac = fmaf(cs.x, d, ac);
            as = fmaf(cs.y, d, as);
        }
        ac += __shfl_xor_sync(0xFFFFFFFFu, ac, 1);   // a+b both lanes: exact, det.
        as += __shfl_xor_sync(0xFFFFFFFFu, as, 1);
        if (!half) sA[i * 4 + pl] = make_float2(ac, as);
    }
    __syncthreads();

    // ---- stage 2: pairs 0..239 -> (pl = tt/60, q = tt%60); halves split i ----
    float re = 0.f, im = 0.f;
    if (tt < 240) {
        const int pl = tt / 60;
        const int q  = tt - pl * 60;
        const int i0 = half * 32;
        float re1 = 0.f, re2 = 0.f, im1 = 0.f, im2 = 0.f;
        #pragma unroll 16
        for (int ii = 0; ii < 32; ii++) {
            int i = i0 + ii;
            float2 a  = sA[i * 4 + pl];      // broadcast
            float2 cs = sCS[i * PP + q];
            re1 = fmaf(a.x, cs.x, re1);
            re2 = fmaf(a.y, cs.y, re2);
            im1 = fmaf(a.y, cs.x, im1);
            im2 = fmaf(a.x, cs.y, im2);
        }
        re = re1 - re2;
        im = im1 + im2;
    }
    re += __shfl_xor_sync(0xFFFFFFFFu, re, 1);       // combine halves (exact)
    im += __shfl_xor_sync(0xFFFFFFFFu, im, 1);
    float v = (!half && tt < 240) ? fmaf(re, re, im * im) : 0.f;

    // ---- block reduce sum of squares ----
    #pragma unroll
    for (int off = 16; off > 0; off >>= 1)
        v += __shfl_down_sync(0xFFFFFFFFu, v, off);

    __syncthreads();                       // stage-2 smem reads done; reuse sD
    if ((t & 31) == 0) sD[t >> 5] = v;     // 16 warp partials
    __syncthreads();
    if (t == 0) {
        float s = 0.f;
        #pragma unroll
        for (int w = 0; w < 16; w++) s += sD[w];
        g_part[blk] = s;
        __threadfence();                   // release g_part before counter bump
        unsigned c = atomicAdd(&g_count, 1u);
        bool last = (c == NBLK - 1);
        if (last) g_count = 0;             // reset for next graph replay
        sD[16] = last ? 1.f : 0.f;         // flag via dynamic smem (no static shared)
    }
    __syncthreads();

    // ---- last block: deterministic finalize ----
    if (sD[16] != 0.f) {
        __threadfence();                   // acquire: all g_part visible
        float w = 0.f;
        if (t < NB) {
            float s = 0.f;
            #pragma unroll
            for (int k = 0; k < PTILES; k++)
                s += g_part[t * PTILES + k];   // fixed order -> deterministic
            w = sqrtf(s);
        }
        if (t < 32) {
            #pragma unroll
            for (int off = 16; off > 0; off >>= 1)
                w += __shfl_down_sync(0xFFFFFFFFu, w, off);
            if (t == 0) out[0] = w * 0.1f / 8.0f;
        }
    }
}

// ---------------------------------------------------------------------------
extern "C" void kernel_launch(void* const* d_in, const int* in_sizes, int n_in,
                              void* d_out, int out_size) {
    (void)in_sizes; (void)n_in; (void)out_size;
    const float* dnn = (const float*)d_in[0];
    const float* gt  = (const float*)d_in[1];
    float* out = (float*)d_out;

    chf_fused_kernel<<<NBLK, NT, 12288 * sizeof(float)>>>(dnn, gt, out);
}